// round 1
// baseline (speedup 1.0000x reference)
#include <cuda_runtime.h>
#include <cstdint>

// Problem constants (fixed by the reference)
#define NN   50000
#define EE   800000
#define DD   128
#define HH   8
#define CC   16
#define EDD  64
#define LL   3

// ---------------- scratch (static device globals; no allocation) -------------
__device__ float  g_q  [NN * DD];
__device__ float  g_k  [NN * DD];
__device__ float  g_v  [NN * DD];
__device__ float  g_out[NN * DD];
__device__ float  g_xa [NN * DD];
__device__ float  g_xb [NN * DD];
__device__ float  g_e  [(size_t)EE * DD];     // 409.6 MB
__device__ float  g_alpha[(size_t)EE * HH];
__device__ int    g_nmax[NN * HH];
__device__ float  g_den [NN * HH];
__device__ double g_sums[2 * DD];
__device__ float2 g_ab  [DD];

// ---------------- helpers ----------------------------------------------------
__device__ __forceinline__ void red_add_v4(float* addr, float4 v) {
    asm volatile("red.global.add.v4.f32 [%0], {%1,%2,%3,%4};"
                 :: "l"(addr), "f"(v.x), "f"(v.y), "f"(v.z), "f"(v.w)
                 : "memory");
}

// ---------------- init per layer ---------------------------------------------
__global__ void init_kernel() {
    int i = blockIdx.x * blockDim.x + threadIdx.x;
    if (i < NN * HH) {
        g_nmax[i] = (int)0x807FFFFF;  // encoded -inf for ordered-int float max
        g_den[i]  = 0.0f;
    }
    if (i < 2 * DD) g_sums[i] = 0.0;
}

// ---------------- classic register-tiled SGEMM: C[M,128] = A[M,K]@B[K,128]+b --
// BM=128, BN=128, BK=8, TM=TN=8, 256 threads
__global__ void sgemm_bias(const float* __restrict__ A, const float* __restrict__ B,
                           const float* __restrict__ bias, float* __restrict__ C,
                           int M, int K) {
    __shared__ float As[8][128];
    __shared__ float Bs[8][128];
    const int tid      = threadIdx.x;
    const int blockRow = blockIdx.x * 128;
    const int tr   = (tid >> 4) * 8;     // 0..120
    const int tc   = (tid & 15) * 8;     // 0..120
    const int aRow = tid >> 1;           // 0..127
    const int aCol = (tid & 1) * 4;      // 0 / 4
    const int bRow = tid >> 5;           // 0..7
    const int bCol = (tid & 31) * 4;     // 0..124

    float acc[8][8];
#pragma unroll
    for (int i = 0; i < 8; i++)
#pragma unroll
        for (int j = 0; j < 8; j++) acc[i][j] = 0.0f;

    const int  gr      = blockRow + aRow;
    const bool arow_ok = (gr < M);
    const float* Aptr  = A + (size_t)gr * K + aCol;

    for (int k0 = 0; k0 < K; k0 += 8) {
        float4 a4 = make_float4(0.f, 0.f, 0.f, 0.f);
        if (arow_ok) a4 = *(const float4*)(Aptr + k0);
        As[aCol + 0][aRow] = a4.x;
        As[aCol + 1][aRow] = a4.y;
        As[aCol + 2][aRow] = a4.z;
        As[aCol + 3][aRow] = a4.w;
        *(float4*)&Bs[bRow][bCol] =
            *(const float4*)(B + (size_t)(k0 + bRow) * 128 + bCol);
        __syncthreads();
#pragma unroll
        for (int kk = 0; kk < 8; kk++) {
            float4 a0 = *(const float4*)&As[kk][tr];
            float4 a1 = *(const float4*)&As[kk][tr + 4];
            float4 b0 = *(const float4*)&Bs[kk][tc];
            float4 b1 = *(const float4*)&Bs[kk][tc + 4];
            float ar[8] = {a0.x, a0.y, a0.z, a0.w, a1.x, a1.y, a1.z, a1.w};
            float br[8] = {b0.x, b0.y, b0.z, b0.w, b1.x, b1.y, b1.z, b1.w};
#pragma unroll
            for (int i = 0; i < 8; i++)
#pragma unroll
                for (int j = 0; j < 8; j++) acc[i][j] += ar[i] * br[j];
        }
        __syncthreads();
    }

#pragma unroll
    for (int i = 0; i < 8; i++) {
        int row = blockRow + tr + i;
        if (row >= M) break;
        float* cp = C + (size_t)row * 128 + tc;
#pragma unroll
        for (int j = 0; j < 8; j += 4) {
            float4 o;
            o.x = acc[i][j + 0] + bias[tc + j + 0];
            o.y = acc[i][j + 1] + bias[tc + j + 1];
            o.z = acc[i][j + 2] + bias[tc + j + 2];
            o.w = acc[i][j + 3] + bias[tc + j + 3];
            *(float4*)(cp + j) = o;
        }
    }
}

// ---------------- pass 1: alpha + segment max (warp per edge) -----------------
__global__ void alpha_kernel(const int* __restrict__ ei) {
    int gw   = (blockIdx.x * blockDim.x + threadIdx.x) >> 5;
    int lane = threadIdx.x & 31;
    if (gw >= EE) return;
    int src = ei[gw];
    int dst = ei[EE + gw];

    float4 q4 = ((const float4*)(g_q + (size_t)dst * DD))[lane];
    float4 k4 = ((const float4*)(g_k + (size_t)src * DD))[lane];
    float4 e4 = ((const float4*)(g_e + (size_t)gw  * DD))[lane];

    float p = q4.x * (k4.x + e4.x) + q4.y * (k4.y + e4.y)
            + q4.z * (k4.z + e4.z) + q4.w * (k4.w + e4.w);
    p += __shfl_xor_sync(0xFFFFFFFFu, p, 1);
    p += __shfl_xor_sync(0xFFFFFFFFu, p, 2);

    if ((lane & 3) == 0) {
        int   h = lane >> 2;
        float a = p * 0.25f;              // / sqrt(C), C=16
        g_alpha[(size_t)gw * HH + h] = a;
        int rep = __float_as_int(a);
        rep = (rep >= 0) ? rep : (rep ^ 0x7FFFFFFF);
        atomicMax(&g_nmax[dst * HH + h], rep);
    }
}

// ---------------- pass 2: exp + segment sum (thread per edge) -----------------
__global__ void exp_kernel(const int* __restrict__ ei) {
    int e = blockIdx.x * blockDim.x + threadIdx.x;
    if (e >= EE) return;
    int dst = ei[EE + e];

    float4 a0 = *((const float4*)(g_alpha + (size_t)e * HH));
    float4 a1 = *((const float4*)(g_alpha + (size_t)e * HH + 4));
    int4 n0 = *((const int4*)(g_nmax + dst * HH));
    int4 n1 = *((const int4*)(g_nmax + dst * HH + 4));

    int enc;
    float4 x0, x1;
    enc = n0.x; enc = (enc >= 0) ? enc : (enc ^ 0x7FFFFFFF); x0.x = __expf(a0.x - __int_as_float(enc));
    enc = n0.y; enc = (enc >= 0) ? enc : (enc ^ 0x7FFFFFFF); x0.y = __expf(a0.y - __int_as_float(enc));
    enc = n0.z; enc = (enc >= 0) ? enc : (enc ^ 0x7FFFFFFF); x0.z = __expf(a0.z - __int_as_float(enc));
    enc = n0.w; enc = (enc >= 0) ? enc : (enc ^ 0x7FFFFFFF); x0.w = __expf(a0.w - __int_as_float(enc));
    enc = n1.x; enc = (enc >= 0) ? enc : (enc ^ 0x7FFFFFFF); x1.x = __expf(a1.x - __int_as_float(enc));
    enc = n1.y; enc = (enc >= 0) ? enc : (enc ^ 0x7FFFFFFF); x1.y = __expf(a1.y - __int_as_float(enc));
    enc = n1.z; enc = (enc >= 0) ? enc : (enc ^ 0x7FFFFFFF); x1.z = __expf(a1.z - __int_as_float(enc));
    enc = n1.w; enc = (enc >= 0) ? enc : (enc ^ 0x7FFFFFFF); x1.w = __expf(a1.w - __int_as_float(enc));

    *((float4*)(g_alpha + (size_t)e * HH))     = x0;
    *((float4*)(g_alpha + (size_t)e * HH + 4)) = x1;
    red_add_v4(g_den + dst * HH,     x0);
    red_add_v4(g_den + dst * HH + 4, x1);
}

// ---------------- pass 3: weighted message scatter (warp per edge) ------------
__global__ void scatter_kernel(const int* __restrict__ ei) {
    int gw   = (blockIdx.x * blockDim.x + threadIdx.x) >> 5;
    int lane = threadIdx.x & 31;
    if (gw >= EE) return;
    int src = ei[gw];
    int dst = ei[EE + gw];
    int h   = lane >> 2;

    float ex = g_alpha[(size_t)gw * HH + h];
    float dn = g_den[dst * HH + h];
    float w  = ex / (dn + 1e-16f);

    float4 v4 = ((const float4*)(g_v + (size_t)src * DD))[lane];
    float4 e4 = ((const float4*)(g_e + (size_t)gw  * DD))[lane];
    float4 m;
    m.x = (v4.x + e4.x) * w;
    m.y = (v4.y + e4.y) * w;
    m.z = (v4.z + e4.z) * w;
    m.w = (v4.w + e4.w) * w;
    red_add_v4(g_out + (size_t)dst * DD + lane * 4, m);
}

// ---------------- BatchNorm: column sums (fp64 accumulate) --------------------
__global__ void bn_sum_kernel() {
    int ch = threadIdx.x;   // 128 threads
    double s = 0.0, s2 = 0.0;
    for (int r = blockIdx.x; r < NN; r += gridDim.x) {
        float v = g_out[(size_t)r * DD + ch];
        s  += (double)v;
        s2 += (double)v * (double)v;
    }
    atomicAdd(&g_sums[ch], s);
    atomicAdd(&g_sums[DD + ch], s2);
}

__global__ void bn_fin_kernel(const float* __restrict__ gamma,
                              const float* __restrict__ beta) {
    int ch = threadIdx.x;
    double mu  = g_sums[ch] / (double)NN;
    double var = g_sums[DD + ch] / (double)NN - mu * mu;
    double rs  = 1.0 / sqrt(var + 1e-5);
    float a = gamma[ch] * (float)rs;
    float b = beta[ch] - (float)mu * a;
    g_ab[ch] = make_float2(a, b);
}

__global__ void bn_apply_kernel(float* __restrict__ xo) {
    int idx = blockIdx.x * blockDim.x + threadIdx.x;
    if (idx >= NN * DD) return;
    int ch = idx & (DD - 1);
    float2 c = g_ab[ch];
    float y = g_out[idx] * c.x + c.y;
    xo[idx] = (y >= 0.0f) ? y : 0.01f * y;
}

// ---------------- driver -------------------------------------------------------
extern "C" void kernel_launch(void* const* d_in, const int* in_sizes, int n_in,
                              void* d_out, int out_size) {
    const float* x     = (const float*)d_in[0];
    const int*   ei    = (const int*)  d_in[1];
    const float* ea    = (const float*)d_in[2];
    const float* Wq    = (const float*)d_in[3];
    const float* bq    = (const float*)d_in[4];
    const float* Wk    = (const float*)d_in[5];
    const float* bk    = (const float*)d_in[6];
    const float* Wv    = (const float*)d_in[7];
    const float* bv    = (const float*)d_in[8];
    const float* We    = (const float*)d_in[9];
    const float* be    = (const float*)d_in[10];
    const float* Ws    = (const float*)d_in[11];
    const float* bs    = (const float*)d_in[12];
    const float* gamma = (const float*)d_in[13];
    const float* beta  = (const float*)d_in[14];
    float* out = (float*)d_out;

    float *q, *k, *v, *ob, *xa, *xb, *e;
    cudaGetSymbolAddress((void**)&q,  g_q);
    cudaGetSymbolAddress((void**)&k,  g_k);
    cudaGetSymbolAddress((void**)&v,  g_v);
    cudaGetSymbolAddress((void**)&ob, g_out);
    cudaGetSymbolAddress((void**)&xa, g_xa);
    cudaGetSymbolAddress((void**)&xb, g_xb);
    cudaGetSymbolAddress((void**)&e,  g_e);

    const int nodeBlocks = (NN + 127) / 128;     // 391
    const int edgeBlocks = EE / 128;             // 6250
    const int warpEdgeBlocks = EE / 8;           // 100000 (8 warps/block)

    const float* xin = x;
    for (int l = 0; l < LL; l++) {
        float* xout = (l == 0) ? xa : ((l == 1) ? xb : out);

        init_kernel<<<(NN * HH + 255) / 256, 256>>>();

        sgemm_bias<<<nodeBlocks, 256>>>(xin, Wq + (size_t)l * DD * DD, bq + l * DD, q,  NN, DD);
        sgemm_bias<<<nodeBlocks, 256>>>(xin, Wk + (size_t)l * DD * DD, bk + l * DD, k,  NN, DD);
        sgemm_bias<<<nodeBlocks, 256>>>(xin, Wv + (size_t)l * DD * DD, bv + l * DD, v,  NN, DD);
        sgemm_bias<<<nodeBlocks, 256>>>(xin, Ws + (size_t)l * DD * DD, bs + l * DD, ob, NN, DD);
        sgemm_bias<<<edgeBlocks, 256>>>(ea,  We + (size_t)l * EDD * DD, be + l * DD, e, EE, EDD);

        alpha_kernel  <<<warpEdgeBlocks, 256>>>(ei);
        exp_kernel    <<<(EE + 255) / 256, 256>>>(ei);
        scatter_kernel<<<warpEdgeBlocks, 256>>>(ei);

        bn_sum_kernel  <<<256, 128>>>();
        bn_fin_kernel  <<<1, 128>>>(gamma + l * DD, beta + l * DD);
        bn_apply_kernel<<<(NN * DD + 255) / 256, 256>>>(xout);

        xin = xout;
    }
}

// round 2
// speedup vs baseline: 1.4360x; 1.4360x over previous
#include <cuda_runtime.h>
#include <cuda_fp16.h>
#include <cstdint>

// Problem constants (fixed by the reference)
#define NN   50000
#define EE   800000
#define DD   128
#define HH   8
#define CC   16
#define EDD  64
#define LL   3

// ---------------- scratch (static device globals; no allocation) -------------
__device__ float  g_q  [NN * DD];
__device__ float  g_k  [NN * DD];
__device__ float  g_v  [NN * DD];
__device__ float  g_out[NN * DD];     // skip (x@Ws+bs), then final pre-BN out
__device__ float  g_msg[NN * DD];     // unnormalized message accumulator
__device__ float  g_xa [NN * DD];
__device__ float  g_xb [NN * DD];
__device__ __half g_e  [(size_t)EE * DD];     // 204.8 MB (fp16)
__device__ float  g_alpha[(size_t)EE * HH];   // raw scores
__device__ int    g_nmax[NN * HH];
__device__ float  g_den [NN * HH];
__device__ double g_sums[2 * DD];
__device__ float2 g_ab  [DD];

// ---------------- helpers ----------------------------------------------------
__device__ __forceinline__ void red_add_v4(float* addr, float4 v) {
    asm volatile("red.global.add.v4.f32 [%0], {%1,%2,%3,%4};"
                 :: "l"(addr), "f"(v.x), "f"(v.y), "f"(v.z), "f"(v.w)
                 : "memory");
}
__device__ __forceinline__ void red_add_f(float* addr, float v) {
    asm volatile("red.global.add.f32 [%0], %1;" :: "l"(addr), "f"(v) : "memory");
}

// ---------------- init per layer ---------------------------------------------
__global__ void init_kernel() {
    int i = blockIdx.x * blockDim.x + threadIdx.x;
    if (i < NN * DD) g_msg[i] = 0.0f;
    if (i < NN * HH) {
        g_nmax[i] = (int)0x807FFFFF;  // encoded -inf for ordered-int float max
        g_den[i]  = 0.0f;
    }
    if (i < 2 * DD) g_sums[i] = 0.0;
}

// ---------------- classic register-tiled SGEMM: C[M,128] = A[M,K]@B[K,128]+b --
// BM=128, BN=128, BK=8, TM=TN=8, 256 threads. Templated on output type.
template <typename OT>
__global__ void sgemm_bias(const float* __restrict__ A, const float* __restrict__ B,
                           const float* __restrict__ bias, OT* __restrict__ C,
                           int M, int K) {
    __shared__ float As[8][128];
    __shared__ float Bs[8][128];
    const int tid      = threadIdx.x;
    const int blockRow = blockIdx.x * 128;
    const int tr   = (tid >> 4) * 8;
    const int tc   = (tid & 15) * 8;
    const int aRow = tid >> 1;
    const int aCol = (tid & 1) * 4;
    const int bRow = tid >> 5;
    const int bCol = (tid & 31) * 4;

    float acc[8][8];
#pragma unroll
    for (int i = 0; i < 8; i++)
#pragma unroll
        for (int j = 0; j < 8; j++) acc[i][j] = 0.0f;

    const int  gr      = blockRow + aRow;
    const bool arow_ok = (gr < M);
    const float* Aptr  = A + (size_t)gr * K + aCol;

    for (int k0 = 0; k0 < K; k0 += 8) {
        float4 a4 = make_float4(0.f, 0.f, 0.f, 0.f);
        if (arow_ok) a4 = *(const float4*)(Aptr + k0);
        As[aCol + 0][aRow] = a4.x;
        As[aCol + 1][aRow] = a4.y;
        As[aCol + 2][aRow] = a4.z;
        As[aCol + 3][aRow] = a4.w;
        *(float4*)&Bs[bRow][bCol] =
            *(const float4*)(B + (size_t)(k0 + bRow) * 128 + bCol);
        __syncthreads();
#pragma unroll
        for (int kk = 0; kk < 8; kk++) {
            float4 a0 = *(const float4*)&As[kk][tr];
            float4 a1 = *(const float4*)&As[kk][tr + 4];
            float4 b0 = *(const float4*)&Bs[kk][tc];
            float4 b1 = *(const float4*)&Bs[kk][tc + 4];
            float ar[8] = {a0.x, a0.y, a0.z, a0.w, a1.x, a1.y, a1.z, a1.w};
            float br[8] = {b0.x, b0.y, b0.z, b0.w, b1.x, b1.y, b1.z, b1.w};
#pragma unroll
            for (int i = 0; i < 8; i++)
#pragma unroll
                for (int j = 0; j < 8; j++) acc[i][j] += ar[i] * br[j];
        }
        __syncthreads();
    }

#pragma unroll
    for (int i = 0; i < 8; i++) {
        int row = blockRow + tr + i;
        if (row >= M) break;
#pragma unroll
        for (int j = 0; j < 8; j += 4) {
            float4 o;
            o.x = acc[i][j + 0] + bias[tc + j + 0];
            o.y = acc[i][j + 1] + bias[tc + j + 1];
            o.z = acc[i][j + 2] + bias[tc + j + 2];
            o.w = acc[i][j + 3] + bias[tc + j + 3];
            if constexpr (sizeof(OT) == 4) {
                *(float4*)((float*)C + (size_t)row * 128 + tc + j) = o;
            } else {
                __half2 h01 = __floats2half2_rn(o.x, o.y);
                __half2 h23 = __floats2half2_rn(o.z, o.w);
                uint2 packed;
                packed.x = *(const unsigned*)&h01;
                packed.y = *(const unsigned*)&h23;
                *(uint2*)((__half*)C + (size_t)row * 128 + tc + j) = packed;
            }
        }
    }
}

// ---------------- pass 1: alpha + segment max (warp per edge) -----------------
__global__ void alpha_kernel(const int* __restrict__ ei) {
    int gw   = (blockIdx.x * blockDim.x + threadIdx.x) >> 5;
    int lane = threadIdx.x & 31;
    if (gw >= EE) return;
    int src = ei[gw];
    int dst = ei[EE + gw];

    float4 q4 = ((const float4*)(g_q + (size_t)dst * DD))[lane];
    float4 k4 = ((const float4*)(g_k + (size_t)src * DD))[lane];
    const __half2* ep = (const __half2*)g_e + (size_t)gw * (DD / 2);
    float2 e0 = __half22float2(ep[2 * lane]);
    float2 e1 = __half22float2(ep[2 * lane + 1]);

    float p = q4.x * (k4.x + e0.x) + q4.y * (k4.y + e0.y)
            + q4.z * (k4.z + e1.x) + q4.w * (k4.w + e1.y);
    p += __shfl_xor_sync(0xFFFFFFFFu, p, 1);
    p += __shfl_xor_sync(0xFFFFFFFFu, p, 2);

    if ((lane & 3) == 0) {
        int   h = lane >> 2;
        float a = p * 0.25f;              // / sqrt(C), C=16
        g_alpha[(size_t)gw * HH + h] = a;
        int rep = __float_as_int(a);
        rep = (rep >= 0) ? rep : (rep ^ 0x7FFFFFFF);
        atomicMax(&g_nmax[dst * HH + h], rep);
    }
}

// ------- pass 2 (merged exp+scatter): unnormalized weighted scatter -----------
__global__ void scatter_kernel(const int* __restrict__ ei) {
    int gw   = (blockIdx.x * blockDim.x + threadIdx.x) >> 5;
    int lane = threadIdx.x & 31;
    if (gw >= EE) return;
    int src = ei[gw];
    int dst = ei[EE + gw];
    int h   = lane >> 2;

    float a   = g_alpha[(size_t)gw * HH + h];
    int   enc = g_nmax[dst * HH + h];
    enc = (enc >= 0) ? enc : (enc ^ 0x7FFFFFFF);
    float ex  = __expf(a - __int_as_float(enc));

    float4 v4 = ((const float4*)(g_v + (size_t)src * DD))[lane];
    const __half2* ep = (const __half2*)g_e + (size_t)gw * (DD / 2);
    float2 e0 = __half22float2(ep[2 * lane]);
    float2 e1 = __half22float2(ep[2 * lane + 1]);

    float4 m;
    m.x = (v4.x + e0.x) * ex;
    m.y = (v4.y + e0.y) * ex;
    m.z = (v4.z + e1.x) * ex;
    m.w = (v4.w + e1.y) * ex;
    red_add_v4(g_msg + (size_t)dst * DD + lane * 4, m);
    if ((lane & 3) == 0) red_add_f(g_den + dst * HH + h, ex);
}

// ---- node pass: normalize + skip add + BN column sums (fp64) -----------------
__global__ void combine_bnsum_kernel() {
    int ch = threadIdx.x;   // 128 threads = 128 channels
    int hd = ch >> 4;       // head of this channel
    double s = 0.0, s2 = 0.0;
    for (int r = blockIdx.x; r < NN; r += gridDim.x) {
        float dn = g_den[r * HH + hd];
        float o  = g_msg[(size_t)r * DD + ch] / (dn + 1e-16f)
                 + g_out[(size_t)r * DD + ch];
        g_out[(size_t)r * DD + ch] = o;
        s  += (double)o;
        s2 += (double)o * (double)o;
    }
    atomicAdd(&g_sums[ch], s);
    atomicAdd(&g_sums[DD + ch], s2);
}

__global__ void bn_fin_kernel(const float* __restrict__ gamma,
                              const float* __restrict__ beta) {
    int ch = threadIdx.x;
    double mu  = g_sums[ch] / (double)NN;
    double var = g_sums[DD + ch] / (double)NN - mu * mu;
    double rs  = 1.0 / sqrt(var + 1e-5);
    float a = gamma[ch] * (float)rs;
    float b = beta[ch] - (float)mu * a;
    g_ab[ch] = make_float2(a, b);
}

__global__ void bn_apply_kernel(float* __restrict__ xo) {
    int idx = blockIdx.x * blockDim.x + threadIdx.x;
    if (idx >= NN * DD) return;
    int ch = idx & (DD - 1);
    float2 c = g_ab[ch];
    float y = g_out[idx] * c.x + c.y;
    xo[idx] = (y >= 0.0f) ? y : 0.01f * y;
}

// ---------------- driver -------------------------------------------------------
extern "C" void kernel_launch(void* const* d_in, const int* in_sizes, int n_in,
                              void* d_out, int out_size) {
    const float* x     = (const float*)d_in[0];
    const int*   ei    = (const int*)  d_in[1];
    const float* ea    = (const float*)d_in[2];
    const float* Wq    = (const float*)d_in[3];
    const float* bq    = (const float*)d_in[4];
    const float* Wk    = (const float*)d_in[5];
    const float* bk    = (const float*)d_in[6];
    const float* Wv    = (const float*)d_in[7];
    const float* bv    = (const float*)d_in[8];
    const float* We    = (const float*)d_in[9];
    const float* be    = (const float*)d_in[10];
    const float* Ws    = (const float*)d_in[11];
    const float* bs    = (const float*)d_in[12];
    const float* gamma = (const float*)d_in[13];
    const float* beta  = (const float*)d_in[14];
    float* out = (float*)d_out;

    float *q, *k, *v, *ob, *xa, *xb;
    __half* e;
    cudaGetSymbolAddress((void**)&q,  g_q);
    cudaGetSymbolAddress((void**)&k,  g_k);
    cudaGetSymbolAddress((void**)&v,  g_v);
    cudaGetSymbolAddress((void**)&ob, g_out);
    cudaGetSymbolAddress((void**)&xa, g_xa);
    cudaGetSymbolAddress((void**)&xb, g_xb);
    cudaGetSymbolAddress((void**)&e,  g_e);

    const int nodeBlocks = (NN + 127) / 128;     // 391
    const int edgeBlocks = EE / 128;             // 6250
    const int warpEdgeBlocks = EE / 8;           // 100000 (8 warps/block)

    const float* xin = x;
    for (int l = 0; l < LL; l++) {
        float* xout = (l == 0) ? xa : ((l == 1) ? xb : out);

        init_kernel<<<(NN * DD + 255) / 256, 256>>>();

        sgemm_bias<float><<<nodeBlocks, 256>>>(xin, Wq + (size_t)l * DD * DD, bq + l * DD, q,  NN, DD);
        sgemm_bias<float><<<nodeBlocks, 256>>>(xin, Wk + (size_t)l * DD * DD, bk + l * DD, k,  NN, DD);
        sgemm_bias<float><<<nodeBlocks, 256>>>(xin, Wv + (size_t)l * DD * DD, bv + l * DD, v,  NN, DD);
        sgemm_bias<float><<<nodeBlocks, 256>>>(xin, Ws + (size_t)l * DD * DD, bs + l * DD, ob, NN, DD);
        sgemm_bias<__half><<<edgeBlocks, 256>>>(ea, We + (size_t)l * EDD * DD, be + l * DD, e, EE, EDD);

        alpha_kernel  <<<warpEdgeBlocks, 256>>>(ei);
        scatter_kernel<<<warpEdgeBlocks, 256>>>(ei);

        combine_bnsum_kernel<<<256, 128>>>();
        bn_fin_kernel       <<<1, 128>>>(gamma + l * DD, beta + l * DD);
        bn_apply_kernel     <<<(NN * DD + 255) / 256, 256>>>(xout);

        xin = xout;
    }
}

// round 4
// speedup vs baseline: 1.7244x; 1.2008x over previous
#include <cuda_runtime.h>
#include <cuda_fp16.h>
#include <cstdint>

// Problem constants (fixed by the reference)
#define NN   50000
#define EE   800000
#define DD   128
#define HH   8
#define CC   16
#define EDD  64
#define LL   3

// ---------------- scratch (static device globals; no allocation) -------------
__device__ float  g_q  [NN * DD];
__device__ float  g_k  [NN * DD];
__device__ float  g_v  [NN * DD];
__device__ float  g_out[NN * DD];     // skip (x@Ws+bs), then final pre-BN out
__device__ float  g_msg[NN * DD];     // unnormalized message accumulator
__device__ float  g_xa [NN * DD];
__device__ float  g_xb [NN * DD];
__device__ __half g_e  [(size_t)EE * DD];      // 204.8 MB (fp16)
__device__ __half g_ea16[(size_t)EE * EDD];    // edge_attr in fp16 (102.4 MB)
__device__ __half g_wet [DD * EDD];            // We^T fp16 [n=128][k=64]
__device__ float  g_alpha[(size_t)EE * HH];    // raw scores
__device__ int    g_nmax[NN * HH];
__device__ float  g_den [NN * HH];
__device__ double g_sums[2 * DD];
__device__ float2 g_ab  [DD];

// ---------------- helpers ----------------------------------------------------
__device__ __forceinline__ uint32_t smem_u32(const void* p) {
    uint32_t a;
    asm("{ .reg .u64 t; cvta.to.shared.u64 t, %1; cvt.u32.u64 %0, t; }" : "=r"(a) : "l"(p));
    return a;
}
__device__ __forceinline__ uint32_t sw128(uint32_t off) { return off ^ ((off >> 3) & 0x70); }

__device__ __forceinline__ void red_add_v4(float* addr, float4 v) {
    asm volatile("red.global.add.v4.f32 [%0], {%1,%2,%3,%4};"
                 :: "l"(addr), "f"(v.x), "f"(v.y), "f"(v.z), "f"(v.w) : "memory");
}
__device__ __forceinline__ void red_add_f(float* addr, float v) {
    asm volatile("red.global.add.f32 [%0], %1;" :: "l"(addr), "f"(v) : "memory");
}
__device__ __forceinline__ void ldmatrix_x4(uint32_t* r, uint32_t addr) {
    asm volatile("ldmatrix.sync.aligned.m8n8.x4.shared.b16 {%0,%1,%2,%3}, [%4];"
                 : "=r"(r[0]), "=r"(r[1]), "=r"(r[2]), "=r"(r[3]) : "r"(addr));
}
__device__ __forceinline__ void mma16816(float* c, const uint32_t* a, const uint32_t* b) {
    asm volatile("mma.sync.aligned.m16n8k16.row.col.f32.f16.f16.f32 "
                 "{%0,%1,%2,%3}, {%4,%5,%6,%7}, {%8,%9}, {%0,%1,%2,%3};"
                 : "+f"(c[0]), "+f"(c[1]), "+f"(c[2]), "+f"(c[3])
                 : "r"(a[0]), "r"(a[1]), "r"(a[2]), "r"(a[3]), "r"(b[0]), "r"(b[1]));
}

// ---------------- one-time / per-layer prep ------------------------------------
__global__ void conv_ea_kernel(const float* __restrict__ ea) {
    size_t i = (size_t)blockIdx.x * blockDim.x + threadIdx.x;   // over float4 units
    size_t n4 = (size_t)EE * EDD / 4;
    if (i >= n4) return;
    float4 f = ((const float4*)ea)[i];
    __half2 h01 = __floats2half2_rn(f.x, f.y);
    __half2 h23 = __floats2half2_rn(f.z, f.w);
    uint2 p;
    p.x = *(const unsigned*)&h01;
    p.y = *(const unsigned*)&h23;
    ((uint2*)g_ea16)[i] = p;
}

__global__ void wet_kernel(const float* __restrict__ We) {   // We [64,128] -> g_wet [128][64]
    int i = blockIdx.x * blockDim.x + threadIdx.x;
    if (i >= DD * EDD) return;
    int n = i / EDD, k = i % EDD;
    g_wet[i] = __float2half(We[k * DD + n]);
}

// ---------------- init per layer ---------------------------------------------
__global__ void init_kernel() {
    int i = blockIdx.x * blockDim.x + threadIdx.x;
    if (i < NN * DD) g_msg[i] = 0.0f;
    if (i < NN * HH) {
        g_nmax[i] = (int)0x807FFFFF;
        g_den[i]  = 0.0f;
    }
    if (i < 2 * DD) g_sums[i] = 0.0;
}

// ---------------- HMMA edge GEMM: e = ea16 @ We^T + be -------------------------
// CTA: 256 threads (8 warps). Tile M=128, N=128, K=64.
// Warp w computes rows [16w, 16w+16) x all 128 cols via mma.m16n8k16.
__global__ void __launch_bounds__(256, 2)
edge_gemm_mma(const float* __restrict__ bias) {
    __shared__ __align__(128) __half sA[128 * 64];   // 16 KB, SW128-swizzled
    __shared__ __align__(128) __half sB[128 * 64];   // 16 KB, SW128-swizzled
    __shared__ float sbias[128];

    const int tid  = threadIdx.x;
    const int wid  = tid >> 5;
    const int lane = tid & 31;
    const size_t tile = blockIdx.x;

    if (tid < 128) sbias[tid] = bias[tid];

    // A tile: 128 rows x 64 fp16 = 1024 x 16B chunks; coalesced loads, swizzled stores
    const uint4* Ag = (const uint4*)(g_ea16 + tile * 128 * EDD);
#pragma unroll
    for (int i = 0; i < 4; i++) {
        int idx = i * 256 + tid;
        uint4 val = Ag[idx];
        *(uint4*)((char*)sA + sw128(idx * 16)) = val;
    }
    // B tile: g_wet [128 n][64 k]
    const uint4* Bg = (const uint4*)g_wet;
#pragma unroll
    for (int i = 0; i < 4; i++) {
        int idx = i * 256 + tid;
        uint4 val = Bg[idx];
        *(uint4*)((char*)sB + sw128(idx * 16)) = val;
    }
    __syncthreads();

    const uint32_t sAu = smem_u32(sA);
    const uint32_t sBu = smem_u32(sB);
    const int mrow = wid * 16;

    // A fragments: 4 k-steps of 16. lanes 0-15 -> rows, lanes>=16 -> k high half.
    uint32_t afrag[4][4];
#pragma unroll
    for (int t = 0; t < 4; t++) {
        uint32_t off = (uint32_t)(mrow + (lane & 15)) * 128 + t * 32 + ((lane >> 4) * 16);
        ldmatrix_x4(afrag[t], sAu + sw128(off));
    }

    float acc[16][4];
#pragma unroll
    for (int i = 0; i < 16; i++)
#pragma unroll
        for (int j = 0; j < 4; j++) acc[i][j] = 0.0f;

#pragma unroll
    for (int t = 0; t < 4; t++) {
#pragma unroll
        for (int np = 0; np < 8; np++) {     // pair of n-tiles per ldmatrix.x4
            int mtx = lane >> 3;             // 0..3
            int n   = np * 16 + ((mtx >> 1) * 8) + (lane & 7);
            int kb  = t * 32 + ((mtx & 1) * 16);
            uint32_t b[4];
            ldmatrix_x4(b, sBu + sw128((uint32_t)n * 128 + kb));
            mma16816(acc[2 * np],     afrag[t], b);
            mma16816(acc[2 * np + 1], afrag[t], b + 2);
        }
    }

    // Epilogue: + bias, convert fp16, store. Thread owns rows m0, m0+8; cols nt*8+(lane%4)*2.
    const int m0 = (int)tile * 128 + mrow + (lane >> 2);
    const int cq = (lane & 3) * 2;
    __half* r0 = g_e + (size_t)m0 * DD;
    __half* r1 = g_e + (size_t)(m0 + 8) * DD;
#pragma unroll
    for (int nt = 0; nt < 16; nt++) {
        int n = nt * 8 + cq;
        float b0 = sbias[n], b1 = sbias[n + 1];
        __half2 h0 = __floats2half2_rn(acc[nt][0] + b0, acc[nt][1] + b1);
        __half2 h1 = __floats2half2_rn(acc[nt][2] + b0, acc[nt][3] + b1);
        *(__half2*)(r0 + n) = h0;
        *(__half2*)(r1 + n) = h1;
    }
}

// ---------------- classic register-tiled SGEMM (node GEMMs, fp32) -------------
__global__ void sgemm_bias(const float* __restrict__ A, const float* __restrict__ B,
                           const float* __restrict__ bias, float* __restrict__ C,
                           int M, int K) {
    __shared__ float As[8][128];
    __shared__ float Bs[8][128];
    const int tid      = threadIdx.x;
    const int blockRow = blockIdx.x * 128;
    const int tr   = (tid >> 4) * 8;
    const int tc   = (tid & 15) * 8;
    const int aRow = tid >> 1;
    const int aCol = (tid & 1) * 4;
    const int bRow = tid >> 5;
    const int bCol = (tid & 31) * 4;

    float acc[8][8];
#pragma unroll
    for (int i = 0; i < 8; i++)
#pragma unroll
        for (int j = 0; j < 8; j++) acc[i][j] = 0.0f;

    const int  gr      = blockRow + aRow;
    const bool arow_ok = (gr < M);
    const float* Aptr  = A + (size_t)gr * K + aCol;

    for (int k0 = 0; k0 < K; k0 += 8) {
        float4 a4 = make_float4(0.f, 0.f, 0.f, 0.f);
        if (arow_ok) a4 = *(const float4*)(Aptr + k0);
        As[aCol + 0][aRow] = a4.x;
        As[aCol + 1][aRow] = a4.y;
        As[aCol + 2][aRow] = a4.z;
        As[aCol + 3][aRow] = a4.w;
        *(float4*)&Bs[bRow][bCol] =
            *(const float4*)(B + (size_t)(k0 + bRow) * 128 + bCol);
        __syncthreads();
#pragma unroll
        for (int kk = 0; kk < 8; kk++) {
            float4 a0 = *(const float4*)&As[kk][tr];
            float4 a1 = *(const float4*)&As[kk][tr + 4];
            float4 b0 = *(const float4*)&Bs[kk][tc];
            float4 b1 = *(const float4*)&Bs[kk][tc + 4];
            float ar[8] = {a0.x, a0.y, a0.z, a0.w, a1.x, a1.y, a1.z, a1.w};
            float br[8] = {b0.x, b0.y, b0.z, b0.w, b1.x, b1.y, b1.z, b1.w};
#pragma unroll
            for (int i = 0; i < 8; i++)
#pragma unroll
                for (int j = 0; j < 8; j++) acc[i][j] += ar[i] * br[j];
        }
        __syncthreads();
    }

#pragma unroll
    for (int i = 0; i < 8; i++) {
        int row = blockRow + tr + i;
        if (row >= M) break;
        float* cp = C + (size_t)row * 128 + tc;
#pragma unroll
        for (int j = 0; j < 8; j += 4) {
            float4 o;
            o.x = acc[i][j + 0] + bias[tc + j + 0];
            o.y = acc[i][j + 1] + bias[tc + j + 1];
            o.z = acc[i][j + 2] + bias[tc + j + 2];
            o.w = acc[i][j + 3] + bias[tc + j + 3];
            *(float4*)(cp + j) = o;
        }
    }
}

// ---------------- pass 1: alpha + segment max (warp per edge) -----------------
__global__ void alpha_kernel(const int* __restrict__ ei) {
    int gw   = (blockIdx.x * blockDim.x + threadIdx.x) >> 5;
    int lane = threadIdx.x & 31;
    if (gw >= EE) return;
    int src = ei[gw];
    int dst = ei[EE + gw];

    float4 q4 = ((const float4*)(g_q + (size_t)dst * DD))[lane];
    float4 k4 = ((const float4*)(g_k + (size_t)src * DD))[lane];
    const __half2* ep = (const __half2*)g_e + (size_t)gw * (DD / 2);
    float2 e0 = __half22float2(ep[2 * lane]);
    float2 e1 = __half22float2(ep[2 * lane + 1]);

    float p = q4.x * (k4.x + e0.x) + q4.y * (k4.y + e0.y)
            + q4.z * (k4.z + e1.x) + q4.w * (k4.w + e1.y);
    p += __shfl_xor_sync(0xFFFFFFFFu, p, 1);
    p += __shfl_xor_sync(0xFFFFFFFFu, p, 2);

    if ((lane & 3) == 0) {
        int   h = lane >> 2;
        float a = p * 0.25f;
        g_alpha[(size_t)gw * HH + h] = a;
        int rep = __float_as_int(a);
        rep = (rep >= 0) ? rep : (rep ^ 0x7FFFFFFF);
        atomicMax(&g_nmax[dst * HH + h], rep);
    }
}

// ------- pass 2 (merged exp+scatter): unnormalized weighted scatter -----------
__global__ void scatter_kernel(const int* __restrict__ ei) {
    int gw   = (blockIdx.x * blockDim.x + threadIdx.x) >> 5;
    int lane = threadIdx.x & 31;
    if (gw >= EE) return;
    int src = ei[gw];
    int dst = ei[EE + gw];
    int h   = lane >> 2;

    float a   = g_alpha[(size_t)gw * HH + h];
    int   enc = g_nmax[dst * HH + h];
    enc = (enc >= 0) ? enc : (enc ^ 0x7FFFFFFF);
    float ex  = __expf(a - __int_as_float(enc));

    float4 v4 = ((const float4*)(g_v + (size_t)src * DD))[lane];
    const __half2* ep = (const __half2*)g_e + (size_t)gw * (DD / 2);
    float2 e0 = __half22float2(ep[2 * lane]);
    float2 e1 = __half22float2(ep[2 * lane + 1]);

    float4 m;
    m.x = (v4.x + e0.x) * ex;
    m.y = (v4.y + e0.y) * ex;
    m.z = (v4.z + e1.x) * ex;
    m.w = (v4.w + e1.y) * ex;
    red_add_v4(g_msg + (size_t)dst * DD + lane * 4, m);
    if ((lane & 3) == 0) red_add_f(g_den + dst * HH + h, ex);
}

// ---- node pass: normalize + skip add + BN column sums (fp64) -----------------
__global__ void combine_bnsum_kernel() {
    int ch = threadIdx.x;
    int hd = ch >> 4;
    double s = 0.0, s2 = 0.0;
    for (int r = blockIdx.x; r < NN; r += gridDim.x) {
        float dn = g_den[r * HH + hd];
        float o  = g_msg[(size_t)r * DD + ch] / (dn + 1e-16f)
                 + g_out[(size_t)r * DD + ch];
        g_out[(size_t)r * DD + ch] = o;
        s  += (double)o;
        s2 += (double)o * (double)o;
    }
    atomicAdd(&g_sums[ch], s);
    atomicAdd(&g_sums[DD + ch], s2);
}

__global__ void bn_fin_kernel(const float* __restrict__ gamma,
                              const float* __restrict__ beta) {
    int ch = threadIdx.x;
    double mu  = g_sums[ch] / (double)NN;
    double var = g_sums[DD + ch] / (double)NN - mu * mu;
    double rs  = 1.0 / sqrt(var + 1e-5);
    float a = gamma[ch] * (float)rs;
    float b = beta[ch] - (float)mu * a;
    g_ab[ch] = make_float2(a, b);
}

__global__ void bn_apply_kernel(float* __restrict__ xo) {
    int idx = blockIdx.x * blockDim.x + threadIdx.x;
    if (idx >= NN * DD) return;
    int ch = idx & (DD - 1);
    float2 c = g_ab[ch];
    float y = g_out[idx] * c.x + c.y;
    xo[idx] = (y >= 0.0f) ? y : 0.01f * y;
}

// ---------------- driver -------------------------------------------------------
extern "C" void kernel_launch(void* const* d_in, const int* in_sizes, int n_in,
                              void* d_out, int out_size) {
    const float* x     = (const float*)d_in[0];
    const int*   ei    = (const int*)  d_in[1];
    const float* ea    = (const float*)d_in[2];
    const float* Wq    = (const float*)d_in[3];
    const float* bq    = (const float*)d_in[4];
    const float* Wk    = (const float*)d_in[5];
    const float* bk    = (const float*)d_in[6];
    const float* Wv    = (const float*)d_in[7];
    const float* bv    = (const float*)d_in[8];
    const float* We    = (const float*)d_in[9];
    const float* be    = (const float*)d_in[10];
    const float* Ws    = (const float*)d_in[11];
    const float* bs    = (const float*)d_in[12];
    const float* gamma = (const float*)d_in[13];
    const float* beta  = (const float*)d_in[14];
    float* out = (float*)d_out;

    float *q, *k, *v, *ob, *xa, *xb;
    cudaGetSymbolAddress((void**)&q,  g_q);
    cudaGetSymbolAddress((void**)&k,  g_k);
    cudaGetSymbolAddress((void**)&v,  g_v);
    cudaGetSymbolAddress((void**)&ob, g_out);
    cudaGetSymbolAddress((void**)&xa, g_xa);
    cudaGetSymbolAddress((void**)&xb, g_xb);

    const int nodeBlocks = (NN + 127) / 128;     // 391
    const int edgeTiles  = EE / 128;             // 6250
    const int warpEdgeBlocks = EE / 8;           // 100000

    // one-time: edge_attr -> fp16
    conv_ea_kernel<<<(int)(((size_t)EE * EDD / 4 + 255) / 256), 256>>>(ea);

    const float* xin = x;
    for (int l = 0; l < LL; l++) {
        float* xout = (l == 0) ? xa : ((l == 1) ? xb : out);

        init_kernel<<<(NN * DD + 255) / 256, 256>>>();
        wet_kernel <<<(DD * EDD + 255) / 256, 256>>>(We + (size_t)l * EDD * DD);

        sgemm_bias<<<nodeBlocks, 256>>>(xin, Wq + (size_t)l * DD * DD, bq + l * DD, q,  NN, DD);
        sgemm_bias<<<nodeBlocks, 256>>>(xin, Wk + (size_t)l * DD * DD, bk + l * DD, k,  NN, DD);
        sgemm_bias<<<nodeBlocks, 256>>>(xin, Wv + (size_t)l * DD * DD, bv + l * DD, v,  NN, DD);
        sgemm_bias<<<nodeBlocks, 256>>>(xin, Ws + (size_t)l * DD * DD, bs + l * DD, ob, NN, DD);

        edge_gemm_mma<<<edgeTiles, 256>>>(be + l * DD);

        alpha_kernel  <<<warpEdgeBlocks, 256>>>(ei);
        scatter_kernel<<<warpEdgeBlocks, 256>>>(ei);

        combine_bnsum_kernel<<<256, 128>>>();
        bn_fin_kernel       <<<1, 128>>>(gamma + l * DD, beta + l * DD);
        bn_apply_kernel     <<<(NN * DD + 255) / 256, 256>>>(xout);

        xin = xout;
    }
}

// round 5
// speedup vs baseline: 2.1158x; 1.2269x over previous
#include <cuda_runtime.h>
#include <cuda_fp16.h>
#include <cstdint>

// Problem constants (fixed by the reference)
#define NN   50000
#define EE   800000
#define DD   128
#define HH   8
#define CC   16
#define EDD  64
#define LL   3

// ---------------- scratch (static device globals; no allocation) -------------
__device__ float  g_q  [NN * DD];
__device__ float  g_k  [NN * DD];
__device__ float  g_v  [NN * DD];
__device__ float  g_out[NN * DD];     // skip (x@Ws+bs), then final pre-BN out
__device__ float  g_msg[NN * DD];     // unnormalized message accumulator
__device__ __half g_xh [NN * DD];     // x split hi
__device__ __half g_xl [NN * DD];     // x split lo
__device__ __half g_e  [(size_t)EE * DD];      // 204.8 MB (fp16)
__device__ __half g_ea16[(size_t)EE * EDD];    // edge_attr in fp16 (102.4 MB)
__device__ __half g_wet [DD * EDD];            // We^T fp16 [n=128][k=64]
__device__ __half g_wallh[512 * DD];           // [Wq|Wk|Wv|Ws]^T hi [512 n][128 k]
__device__ __half g_walll[512 * DD];           // lo part
__device__ float  g_ball [512];                // [bq|bk|bv|bs]
__device__ float  g_alpha[(size_t)EE * HH];    // raw scores
__device__ int    g_nmax[NN * HH];
__device__ float  g_den [NN * HH];
__device__ double g_sums[2 * DD];
__device__ float2 g_ab  [DD];

// ---------------- helpers ----------------------------------------------------
__device__ __forceinline__ uint32_t smem_u32(const void* p) {
    uint32_t a;
    asm("{ .reg .u64 t; cvta.to.shared.u64 t, %1; cvt.u32.u64 %0, t; }" : "=r"(a) : "l"(p));
    return a;
}
__device__ __forceinline__ uint32_t sw128(uint32_t off) { return off ^ ((off >> 3) & 0x70); }
__device__ __forceinline__ uint32_t sw64 (uint32_t off) { return off ^ ((off >> 3) & 0x30); }

__device__ __forceinline__ void red_add_v4(float* addr, float4 v) {
    asm volatile("red.global.add.v4.f32 [%0], {%1,%2,%3,%4};"
                 :: "l"(addr), "f"(v.x), "f"(v.y), "f"(v.z), "f"(v.w) : "memory");
}
__device__ __forceinline__ void red_add_f(float* addr, float v) {
    asm volatile("red.global.add.f32 [%0], %1;" :: "l"(addr), "f"(v) : "memory");
}
__device__ __forceinline__ void ldmatrix_x4(uint32_t* r, uint32_t addr) {
    asm volatile("ldmatrix.sync.aligned.m8n8.x4.shared.b16 {%0,%1,%2,%3}, [%4];"
                 : "=r"(r[0]), "=r"(r[1]), "=r"(r[2]), "=r"(r[3]) : "r"(addr));
}
__device__ __forceinline__ void mma16816(float* c, const uint32_t* a, const uint32_t* b) {
    asm volatile("mma.sync.aligned.m16n8k16.row.col.f32.f16.f16.f32 "
                 "{%0,%1,%2,%3}, {%4,%5,%6,%7}, {%8,%9}, {%0,%1,%2,%3};"
                 : "+f"(c[0]), "+f"(c[1]), "+f"(c[2]), "+f"(c[3])
                 : "r"(a[0]), "r"(a[1]), "r"(a[2]), "r"(a[3]), "r"(b[0]), "r"(b[1]));
}

// ---------------- one-time / per-layer prep ------------------------------------
__global__ void conv_ea_kernel(const float* __restrict__ ea) {
    size_t i = (size_t)blockIdx.x * blockDim.x + threadIdx.x;   // float4 units
    size_t n4 = (size_t)EE * EDD / 4;
    if (i >= n4) return;
    float4 f = ((const float4*)ea)[i];
    __half2 h01 = __floats2half2_rn(f.x, f.y);
    __half2 h23 = __floats2half2_rn(f.z, f.w);
    uint2 p;
    p.x = *(const unsigned*)&h01;
    p.y = *(const unsigned*)&h23;
    ((uint2*)g_ea16)[i] = p;
}

__global__ void xsplit0_kernel(const float* __restrict__ x) {
    int i = blockIdx.x * blockDim.x + threadIdx.x;
    if (i >= NN * DD) return;
    float f = x[i];
    __half h = __float2half(f);
    g_xh[i] = h;
    g_xl[i] = __float2half(f - __half2float(h));
}

__global__ void wet_kernel(const float* __restrict__ We) {   // We [64,128] -> g_wet [128][64]
    int i = blockIdx.x * blockDim.x + threadIdx.x;
    if (i >= DD * EDD) return;
    int n = i / EDD, k = i % EDD;
    g_wet[i] = __float2half(We[k * DD + n]);
}

// Build [Wq|Wk|Wv|Ws]^T in split fp16 + concatenated bias.
__global__ void wall_prep_kernel(const float* __restrict__ Wq, const float* __restrict__ Wk,
                                 const float* __restrict__ Wv, const float* __restrict__ Ws,
                                 const float* __restrict__ bq, const float* __restrict__ bk,
                                 const float* __restrict__ bv, const float* __restrict__ bs) {
    int i = blockIdx.x * blockDim.x + threadIdx.x;
    if (i >= 512 * DD) return;
    int ng = i / DD;           // 0..511
    int k  = i % DD;
    int mtx = ng >> 7, nloc = ng & 127;
    const float* W = (mtx == 0) ? Wq : (mtx == 1) ? Wk : (mtx == 2) ? Wv : Ws;
    float w = W[k * DD + nloc];
    __half h = __float2half(w);
    g_wallh[i] = h;
    g_walll[i] = __float2half(w - __half2float(h));
    if (i < 512) {
        int m2 = i >> 7, l2 = i & 127;
        const float* b = (m2 == 0) ? bq : (m2 == 1) ? bk : (m2 == 2) ? bv : bs;
        g_ball[i] = b[l2];
    }
}

// ---------------- init per layer ---------------------------------------------
__global__ void init_kernel() {
    int i = blockIdx.x * blockDim.x + threadIdx.x;
    if (i < NN * DD) g_msg[i] = 0.0f;
    if (i < NN * HH) {
        g_nmax[i] = (int)0x807FFFFF;
        g_den[i]  = 0.0f;
    }
    if (i < 2 * DD) g_sums[i] = 0.0;
}

// ------------- fused node GEMM (split-fp16 HMMA): [q|k|v|skip] -----------------
// Grid: 391 M-tiles x 4 N-tiles (blockIdx.x: ntile = bx&3 -> L2 reuse of A).
// CTA 256 thr / 8 warps; tile M=128, N=128; K chunks of 32 halves (64B rows, SW64).
__global__ void __launch_bounds__(256, 2)
node_gemm_mma(float* __restrict__ oq, float* __restrict__ okk,
              float* __restrict__ ov, float* __restrict__ os) {
    __shared__ __align__(128) __half sAh[128 * 32];
    __shared__ __align__(128) __half sAl[128 * 32];
    __shared__ __align__(128) __half sBh[128 * 32];
    __shared__ __align__(128) __half sBl[128 * 32];
    __shared__ float sbias[128];

    const int tid  = threadIdx.x;
    const int wid  = tid >> 5;
    const int lane = tid & 31;
    const int ntile = blockIdx.x & 3;
    const int mbase = (blockIdx.x >> 2) * 128;

    if (tid < 128) sbias[tid] = g_ball[ntile * 128 + tid];

    float acc[16][4];
#pragma unroll
    for (int i = 0; i < 16; i++)
#pragma unroll
        for (int j = 0; j < 4; j++) acc[i][j] = 0.0f;

    const uint32_t sAhu = smem_u32(sAh);
    const uint32_t sAlu = smem_u32(sAl);
    const uint32_t sBhu = smem_u32(sBh);
    const uint32_t sBlu = smem_u32(sBl);
    const int mrow = wid * 16;

    for (int kc = 0; kc < 4; kc++) {
        // A: 128 rows x 32 halves, hi & lo (512 uint4 each)
#pragma unroll
        for (int i = 0; i < 2; i++) {
            int idx = i * 256 + tid;
            int row = idx >> 2, unit = idx & 3;
            int grow = mbase + row;
            uint4 vh = make_uint4(0, 0, 0, 0), vl = make_uint4(0, 0, 0, 0);
            if (grow < NN) {
                size_t g = (size_t)grow * DD + kc * 32 + unit * 8;
                vh = *(const uint4*)(g_xh + g);
                vl = *(const uint4*)(g_xl + g);
            }
            *(uint4*)((char*)sAh + sw64(idx * 16)) = vh;
            *(uint4*)((char*)sAl + sw64(idx * 16)) = vl;
        }
        // B: 128 n x 32 halves
#pragma unroll
        for (int i = 0; i < 2; i++) {
            int idx = i * 256 + tid;
            int row = idx >> 2, unit = idx & 3;
            size_t g = (size_t)(ntile * 128 + row) * DD + kc * 32 + unit * 8;
            *(uint4*)((char*)sBh + sw64(idx * 16)) = *(const uint4*)(g_wallh + g);
            *(uint4*)((char*)sBl + sw64(idx * 16)) = *(const uint4*)(g_walll + g);
        }
        __syncthreads();

#pragma unroll
        for (int t = 0; t < 2; t++) {
            uint32_t ah[4], al[4];
            uint32_t aoff = (uint32_t)(mrow + (lane & 15)) * 64 + t * 32 + ((lane >> 4) * 16);
            ldmatrix_x4(ah, sAhu + sw64(aoff));
            ldmatrix_x4(al, sAlu + sw64(aoff));
#pragma unroll
            for (int np = 0; np < 8; np++) {
                int mtx = lane >> 3;
                uint32_t boff = (uint32_t)(np * 16 + ((mtx >> 1) * 8) + (lane & 7)) * 64
                              + t * 32 + ((mtx & 1) * 16);
                uint32_t bh[4], bl[4];
                ldmatrix_x4(bh, sBhu + sw64(boff));
                ldmatrix_x4(bl, sBlu + sw64(boff));
                mma16816(acc[2 * np],     ah, bh);
                mma16816(acc[2 * np],     ah, bl);
                mma16816(acc[2 * np],     al, bh);
                mma16816(acc[2 * np + 1], ah, bh + 2);
                mma16816(acc[2 * np + 1], ah, bl + 2);
                mma16816(acc[2 * np + 1], al, bh + 2);
            }
        }
        __syncthreads();
    }

    float* dst = (ntile == 0) ? oq : (ntile == 1) ? okk : (ntile == 2) ? ov : os;
    const int r0 = mbase + mrow + (lane >> 2);
    const int cq = (lane & 3) * 2;
#pragma unroll
    for (int nt = 0; nt < 16; nt++) {
        int n = nt * 8 + cq;
        float b0 = sbias[n], b1 = sbias[n + 1];
        if (r0 < NN)
            *(float2*)(dst + (size_t)r0 * DD + n) = make_float2(acc[nt][0] + b0, acc[nt][1] + b1);
        if (r0 + 8 < NN)
            *(float2*)(dst + (size_t)(r0 + 8) * DD + n) = make_float2(acc[nt][2] + b0, acc[nt][3] + b1);
    }
}

// ---------------- HMMA edge GEMM + fused alpha ---------------------------------
// e = ea16 @ We^T + be ; alpha = dot_h(q[dst], k[src]+e)/4 ; segment max.
__global__ void __launch_bounds__(256, 2)
edge_gemm_mma(const float* __restrict__ bias, const int* __restrict__ ei) {
    __shared__ __align__(128) __half sA[128 * 64];   // SW128
    __shared__ __align__(128) __half sB[128 * 64];
    __shared__ float sbias[128];

    const int tid  = threadIdx.x;
    const int wid  = tid >> 5;
    const int lane = tid & 31;
    const size_t tile = blockIdx.x;

    if (tid < 128) sbias[tid] = bias[tid];

    const uint4* Ag = (const uint4*)(g_ea16 + tile * 128 * EDD);
#pragma unroll
    for (int i = 0; i < 4; i++) {
        int idx = i * 256 + tid;
        uint4 val = Ag[idx];
        *(uint4*)((char*)sA + sw128(idx * 16)) = val;
    }
    const uint4* Bg = (const uint4*)g_wet;
#pragma unroll
    for (int i = 0; i < 4; i++) {
        int idx = i * 256 + tid;
        uint4 val = Bg[idx];
        *(uint4*)((char*)sB + sw128(idx * 16)) = val;
    }
    __syncthreads();

    const uint32_t sAu = smem_u32(sA);
    const uint32_t sBu = smem_u32(sB);
    const int mrow = wid * 16;

    uint32_t afrag[4][4];
#pragma unroll
    for (int t = 0; t < 4; t++) {
        uint32_t off = (uint32_t)(mrow + (lane & 15)) * 128 + t * 32 + ((lane >> 4) * 16);
        ldmatrix_x4(afrag[t], sAu + sw128(off));
    }

    float acc[16][4];
#pragma unroll
    for (int i = 0; i < 16; i++)
#pragma unroll
        for (int j = 0; j < 4; j++) acc[i][j] = 0.0f;

#pragma unroll
    for (int t = 0; t < 4; t++) {
#pragma unroll
        for (int np = 0; np < 8; np++) {
            int mtx = lane >> 3;
            int n   = np * 16 + ((mtx >> 1) * 8) + (lane & 7);
            int kb  = t * 32 + ((mtx & 1) * 16);
            uint32_t b[4];
            ldmatrix_x4(b, sBu + sw128((uint32_t)n * 128 + kb));
            mma16816(acc[2 * np],     afrag[t], b);
            mma16816(acc[2 * np + 1], afrag[t], b + 2);
        }
    }

    // Epilogue: bias, store e (fp16), fused alpha.
    const int e0r = (int)tile * 128 + mrow + (lane >> 2);
    const int e1r = e0r + 8;
    const int cq  = (lane & 3) * 2;
    const int src0 = ei[e0r], dst0 = ei[EE + e0r];
    const int src1 = ei[e1r], dst1 = ei[EE + e1r];
    const float* q0 = g_q + (size_t)dst0 * DD;
    const float* k0 = g_k + (size_t)src0 * DD;
    const float* q1 = g_q + (size_t)dst1 * DD;
    const float* k1 = g_k + (size_t)src1 * DD;
    __half* e0p = g_e + (size_t)e0r * DD;
    __half* e1p = g_e + (size_t)e1r * DD;

    float ps0[8], ps1[8];
#pragma unroll
    for (int h = 0; h < 8; h++) { ps0[h] = 0.0f; ps1[h] = 0.0f; }

#pragma unroll
    for (int nt = 0; nt < 16; nt++) {
        int n = nt * 8 + cq;
        int h = nt >> 1;
        float b0 = sbias[n], b1 = sbias[n + 1];
        float ea0 = acc[nt][0] + b0, ea1 = acc[nt][1] + b1;
        float eb0 = acc[nt][2] + b0, eb1 = acc[nt][3] + b1;
        *(__half2*)(e0p + n) = __floats2half2_rn(ea0, ea1);
        *(__half2*)(e1p + n) = __floats2half2_rn(eb0, eb1);
        float2 qa = *(const float2*)(q0 + n);
        float2 ka = *(const float2*)(k0 + n);
        float2 qb = *(const float2*)(q1 + n);
        float2 kb = *(const float2*)(k1 + n);
        ps0[h] += qa.x * (ka.x + ea0) + qa.y * (ka.y + ea1);
        ps1[h] += qb.x * (kb.x + eb0) + qb.y * (kb.y + eb1);
    }
#pragma unroll
    for (int h = 0; h < 8; h++) {
        ps0[h] += __shfl_xor_sync(0xFFFFFFFFu, ps0[h], 1);
        ps0[h] += __shfl_xor_sync(0xFFFFFFFFu, ps0[h], 2);
        ps1[h] += __shfl_xor_sync(0xFFFFFFFFu, ps1[h], 1);
        ps1[h] += __shfl_xor_sync(0xFFFFFFFFu, ps1[h], 2);
    }
    const int qid = lane & 3;
#pragma unroll
    for (int h = 0; h < 8; h++) {
        if ((h & 3) == qid) {
            float a0 = ps0[h] * 0.25f;
            g_alpha[(size_t)e0r * HH + h] = a0;
            int rep = __float_as_int(a0);
            rep = (rep >= 0) ? rep : (rep ^ 0x7FFFFFFF);
            atomicMax(&g_nmax[dst0 * HH + h], rep);
            float a1 = ps1[h] * 0.25f;
            g_alpha[(size_t)e1r * HH + h] = a1;
            rep = __float_as_int(a1);
            rep = (rep >= 0) ? rep : (rep ^ 0x7FFFFFFF);
            atomicMax(&g_nmax[dst1 * HH + h], rep);
        }
    }
}

// ------- pass 2 (merged exp+scatter): unnormalized weighted scatter -----------
__global__ void scatter_kernel(const int* __restrict__ ei) {
    int gw   = (blockIdx.x * blockDim.x + threadIdx.x) >> 5;
    int lane = threadIdx.x & 31;
    if (gw >= EE) return;
    int src = ei[gw];
    int dst = ei[EE + gw];
    int h   = lane >> 2;

    float a   = g_alpha[(size_t)gw * HH + h];
    int   enc = g_nmax[dst * HH + h];
    enc = (enc >= 0) ? enc : (enc ^ 0x7FFFFFFF);
    float ex  = __expf(a - __int_as_float(enc));

    float4 v4 = ((const float4*)(g_v + (size_t)src * DD))[lane];
    const __half2* ep = (const __half2*)g_e + (size_t)gw * (DD / 2);
    float2 e0 = __half22float2(ep[2 * lane]);
    float2 e1 = __half22float2(ep[2 * lane + 1]);

    float4 m;
    m.x = (v4.x + e0.x) * ex;
    m.y = (v4.y + e0.y) * ex;
    m.z = (v4.z + e1.x) * ex;
    m.w = (v4.w + e1.y) * ex;
    red_add_v4(g_msg + (size_t)dst * DD + lane * 4, m);
    if ((lane & 3) == 0) red_add_f(g_den + dst * HH + h, ex);
}

// ---- node pass: normalize + skip add + BN column sums (fp64) -----------------
__global__ void combine_bnsum_kernel() {
    int ch = threadIdx.x;
    int hd = ch >> 4;
    double s = 0.0, s2 = 0.0;
    for (int r = blockIdx.x; r < NN; r += gridDim.x) {
        float dn = g_den[r * HH + hd];
        float o  = g_msg[(size_t)r * DD + ch] / (dn + 1e-16f)
                 + g_out[(size_t)r * DD + ch];
        g_out[(size_t)r * DD + ch] = o;
        s  += (double)o;
        s2 += (double)o * (double)o;
    }
    atomicAdd(&g_sums[ch], s);
    atomicAdd(&g_sums[DD + ch], s2);
}

__global__ void bn_fin_kernel(const float* __restrict__ gamma,
                              const float* __restrict__ beta) {
    int ch = threadIdx.x;
    double mu  = g_sums[ch] / (double)NN;
    double var = g_sums[DD + ch] / (double)NN - mu * mu;
    double rs  = 1.0 / sqrt(var + 1e-5);
    float a = gamma[ch] * (float)rs;
    float b = beta[ch] - (float)mu * a;
    g_ab[ch] = make_float2(a, b);
}

// BN apply + LeakyReLU; writes split-fp16 x for next layer, fp32 only when last.
__global__ void bn_apply_kernel(float* __restrict__ xo, int write_f32) {
    int idx = blockIdx.x * blockDim.x + threadIdx.x;
    if (idx >= NN * DD) return;
    int ch = idx & (DD - 1);
    float2 c = g_ab[ch];
    float y = g_out[idx] * c.x + c.y;
    y = (y >= 0.0f) ? y : 0.01f * y;
    __half h = __float2half(y);
    g_xh[idx] = h;
    g_xl[idx] = __float2half(y - __half2float(h));
    if (write_f32) xo[idx] = y;
}

// ---------------- driver -------------------------------------------------------
extern "C" void kernel_launch(void* const* d_in, const int* in_sizes, int n_in,
                              void* d_out, int out_size) {
    const float* x     = (const float*)d_in[0];
    const int*   ei    = (const int*)  d_in[1];
    const float* ea    = (const float*)d_in[2];
    const float* Wq    = (const float*)d_in[3];
    const float* bq    = (const float*)d_in[4];
    const float* Wk    = (const float*)d_in[5];
    const float* bk    = (const float*)d_in[6];
    const float* Wv    = (const float*)d_in[7];
    const float* bv    = (const float*)d_in[8];
    const float* We    = (const float*)d_in[9];
    const float* be    = (const float*)d_in[10];
    const float* Ws    = (const float*)d_in[11];
    const float* bs    = (const float*)d_in[12];
    const float* gamma = (const float*)d_in[13];
    const float* beta  = (const float*)d_in[14];
    float* out = (float*)d_out;

    float *q, *k, *v, *ob;
    cudaGetSymbolAddress((void**)&q,  g_q);
    cudaGetSymbolAddress((void**)&k,  g_k);
    cudaGetSymbolAddress((void**)&v,  g_v);
    cudaGetSymbolAddress((void**)&ob, g_out);

    const int edgeTiles      = EE / 128;          // 6250
    const int warpEdgeBlocks = EE / 8;            // 100000
    const int nodeGemmBlocks = ((NN + 127) / 128) * 4;  // 1564

    // one-time: edge_attr -> fp16, x -> split fp16
    conv_ea_kernel<<<(int)(((size_t)EE * EDD / 4 + 255) / 256), 256>>>(ea);
    xsplit0_kernel<<<(NN * DD + 255) / 256, 256>>>(x);

    for (int l = 0; l < LL; l++) {
        init_kernel<<<(NN * DD + 255) / 256, 256>>>();
        wet_kernel <<<(DD * EDD + 255) / 256, 256>>>(We + (size_t)l * EDD * DD);
        wall_prep_kernel<<<(512 * DD + 255) / 256, 256>>>(
            Wq + (size_t)l * DD * DD, Wk + (size_t)l * DD * DD,
            Wv + (size_t)l * DD * DD, Ws + (size_t)l * DD * DD,
            bq + l * DD, bk + l * DD, bv + l * DD, bs + l * DD);

        node_gemm_mma<<<nodeGemmBlocks, 256>>>(q, k, v, ob);

        edge_gemm_mma<<<edgeTiles, 256>>>(be + l * DD, ei);

        scatter_kernel<<<warpEdgeBlocks, 256>>>(ei);

        combine_bnsum_kernel<<<256, 128>>>();
        bn_fin_kernel       <<<1, 128>>>(gamma + l * DD, beta + l * DD);
        bn_apply_kernel     <<<(NN * DD + 255) / 256, 256>>>(out, (l == LL - 1) ? 1 : 0);
    }
}